// round 13
// baseline (speedup 1.0000x reference)
#include <cuda_runtime.h>
#include <cstdint>
#include <cstdio>

// Problem constants (fixed by the dataset)
#define N_NODES 50000
#define E_MAX   800000
#define D_HID   256
#define D_OUT   128

// ---------------- device scratch (no allocations allowed) ----------------
__device__ int   g_is64;
__device__ int   g_row[E_MAX];
__device__ int   g_col[E_MAX];
__device__ int   g_outdeg[N_NODES];
__device__ int   g_indeg[N_NODES];
__device__ int   g_fill[N_NODES];
__device__ int   g_off[N_NODES + 1];
__device__ int   g_csr_src[E_MAX];
__device__ float g_csr_norm[E_MAX];

__device__ float g_xw[(size_t)N_NODES * D_HID];
__device__ float g_bufA[(size_t)N_NODES * D_HID];
__device__ float g_bufB[(size_t)N_NODES * D_HID];

// ---------------- dtype detection: int64 vs int32 edge_index ----------------
// If int64: high 32-bit words (odd positions) are all zero (indices < 2^31, nonneg).
// If int32: odd positions are random indices in [0, 50000) -> essentially never all zero.
__global__ void detect_kernel(const int* __restrict__ ei_words) {
    __shared__ int nz;
    if (threadIdx.x == 0) nz = 0;
    __syncthreads();
    int w = ei_words[threadIdx.x * 2 + 1];   // odd words 1,3,...,127
    if (w != 0) atomicAdd(&nz, 1);
    __syncthreads();
    if (threadIdx.x == 0) g_is64 = (nz == 0) ? 1 : 0;
}

__global__ void convert_kernel(const void* __restrict__ ei, int E) {
    int i = blockIdx.x * blockDim.x + threadIdx.x;
    if (i >= E) return;
    if (g_is64) {
        const long long* p = (const long long*)ei;
        g_row[i] = (int)p[i];
        g_col[i] = (int)p[(size_t)E + i];
    } else {
        const int* p = (const int*)ei;
        g_row[i] = p[i];
        g_col[i] = p[E + i];
    }
}

__global__ void zero_kernel(int N) {
    int i = blockIdx.x * blockDim.x + threadIdx.x;
    if (i < N) { g_outdeg[i] = 0; g_indeg[i] = 0; g_fill[i] = 0; }
}

__global__ void degree_kernel(int E) {
    int i = blockIdx.x * blockDim.x + threadIdx.x;
    if (i >= E) return;
    atomicAdd(&g_outdeg[g_row[i]], 1);
    atomicAdd(&g_indeg[g_col[i]], 1);
}

// Single-block exclusive scan of g_indeg -> g_off (N up to 50000, 1024 threads).
__global__ void scan_kernel(int N) {
    __shared__ int sm[1024];
    __shared__ int carry;
    int tid = threadIdx.x;
    if (tid == 0) carry = 0;
    __syncthreads();
    for (int base = 0; base < N; base += 1024) {
        int idx = base + tid;
        int v = (idx < N) ? g_indeg[idx] : 0;
        sm[tid] = v;
        __syncthreads();
        // inclusive Hillis-Steele
        #pragma unroll
        for (int off = 1; off < 1024; off <<= 1) {
            int t = sm[tid];
            int add = (tid >= off) ? sm[tid - off] : 0;
            __syncthreads();
            sm[tid] = t + add;
            __syncthreads();
        }
        int incl = sm[tid];
        int c = carry;          // read before update
        if (idx < N) g_off[idx] = c + incl - v;
        int total = sm[1023];
        __syncthreads();
        if (tid == 0) carry = c + total;
        __syncthreads();
    }
    if (tid == 0) g_off[N] = carry;
}

__global__ void csr_kernel(int E) {
    int e = blockIdx.x * blockDim.x + threadIdx.x;
    if (e >= E) return;
    int r = g_row[e], c = g_col[e];
    int pos = g_off[c] + atomicAdd(&g_fill[c], 1);
    g_csr_src[pos]  = r;
    g_csr_norm[pos] = rsqrtf((float)g_outdeg[r] * (float)g_indeg[c]);
}

// ---------------- fused dual GEMM: xw = A@W ; lin = A@LW + bias ----------------
// A: [M, K] row-major (K=256). W, LW: [K, Dout] row-major. Dout in {128, 256}.
// grid.x over 128-row tiles, grid.y over 2*Dout/128 column/matrix tiles.
__global__ __launch_bounds__(256) void gemm_dual_kernel(
    const float* __restrict__ A, const float* __restrict__ W,
    const float* __restrict__ LW, const float* __restrict__ bias,
    float* __restrict__ xwOut, float* __restrict__ linOut,
    int M, int K, int Dout)
{
    __shared__ float As[16][132];   // transposed A tile, padded
    __shared__ float Bs[16][132];

    int tid = threadIdx.x;
    int ntile = Dout >> 7;                    // 128-col tiles per matrix
    int by = blockIdx.y;
    bool isLin = (by >= ntile);
    const float* B = isLin ? LW : W;
    int colBase = (by % ntile) * 128;
    int rowBase = blockIdx.x * 128;

    int tx = tid & 15;
    int ty = tid >> 4;

    float creg[8][8];
    #pragma unroll
    for (int i = 0; i < 8; i++)
        #pragma unroll
        for (int j = 0; j < 8; j++) creg[i][j] = 0.f;

    for (int kt = 0; kt < K; kt += 16) {
        #pragma unroll
        for (int l = 0; l < 2; l++) {
            int idx = tid + l * 256;
            // A tile: 128 rows x 16 cols = 512 float4
            int ar = idx >> 2;
            int ac = (idx & 3) * 4;
            float4 av = make_float4(0.f, 0.f, 0.f, 0.f);
            int gr = rowBase + ar;
            if (gr < M)
                av = *reinterpret_cast<const float4*>(A + (size_t)gr * K + kt + ac);
            As[ac + 0][ar] = av.x;
            As[ac + 1][ar] = av.y;
            As[ac + 2][ar] = av.z;
            As[ac + 3][ar] = av.w;
            // B tile: 16 rows x 128 cols = 512 float4
            int br = idx >> 5;
            int bc = (idx & 31) * 4;
            float4 bv = *reinterpret_cast<const float4*>(B + (size_t)(kt + br) * Dout + colBase + bc);
            *reinterpret_cast<float4*>(&Bs[br][bc]) = bv;
        }
        __syncthreads();
        #pragma unroll
        for (int kk = 0; kk < 16; kk++) {
            float4 a0 = *reinterpret_cast<const float4*>(&As[kk][ty * 8]);
            float4 a1 = *reinterpret_cast<const float4*>(&As[kk][ty * 8 + 4]);
            float4 b0 = *reinterpret_cast<const float4*>(&Bs[kk][tx * 8]);
            float4 b1 = *reinterpret_cast<const float4*>(&Bs[kk][tx * 8 + 4]);
            float a[8] = {a0.x, a0.y, a0.z, a0.w, a1.x, a1.y, a1.z, a1.w};
            float b[8] = {b0.x, b0.y, b0.z, b0.w, b1.x, b1.y, b1.z, b1.w};
            #pragma unroll
            for (int i = 0; i < 8; i++)
                #pragma unroll
                for (int j = 0; j < 8; j++)
                    creg[i][j] = fmaf(a[i], b[j], creg[i][j]);
        }
        __syncthreads();
    }

    float* Cout = isLin ? linOut : xwOut;
    #pragma unroll
    for (int i = 0; i < 8; i++) {
        int r = rowBase + ty * 8 + i;
        if (r >= M) continue;
        int c = colBase + tx * 8;
        float o[8];
        #pragma unroll
        for (int j = 0; j < 8; j++) {
            float v = creg[i][j];
            if (isLin) v += bias[c + j];
            o[j] = v;
        }
        *reinterpret_cast<float4*>(Cout + (size_t)r * Dout + c)     = make_float4(o[0], o[1], o[2], o[3]);
        *reinterpret_cast<float4*>(Cout + (size_t)r * Dout + c + 4) = make_float4(o[4], o[5], o[6], o[7]);
    }
}

// ---------------- aggregation: out[n] = act( lin[n] + sum_e norm[e]*xw[src[e]] ) ----
// One block per destination node, blockDim == Dout. act: 0 = relu, 1 = sigmoid.
__global__ void aggregate_kernel(const float* __restrict__ xw,
                                 const float* __restrict__ lin,
                                 float* __restrict__ out,
                                 int Dout, int act)
{
    __shared__ int   s_src[128];
    __shared__ float s_nrm[128];
    int n = blockIdx.x;
    int f = threadIdx.x;     // < Dout
    int beg = g_off[n], end = g_off[n + 1];
    float sum = 0.f;
    for (int cb = beg; cb < end; cb += 128) {
        int cnt = min(128, end - cb);
        __syncthreads();
        if (f < cnt) {
            s_src[f] = g_csr_src[cb + f];
            s_nrm[f] = g_csr_norm[cb + f];
        }
        __syncthreads();
        #pragma unroll 4
        for (int i = 0; i < cnt; i++)
            sum = fmaf(s_nrm[i], __ldg(&xw[(size_t)s_src[i] * Dout + f]), sum);
    }
    float v = lin[(size_t)n * Dout + f] + sum;
    if (act)
        v = 1.f / (1.f + expf(-v));
    else
        v = fmaxf(v, 0.f);
    out[(size_t)n * Dout + f] = v;
}

// ---------------- launch ----------------
extern "C" void kernel_launch(void* const* d_in, const int* in_sizes, int n_in,
                              void* d_out, int out_size) {
    const float* x   = (const float*)d_in[0];
    const void*  ei  = d_in[1];
    // d_in[2] = batch (unused)
    const float* w1  = (const float*)d_in[3];
    const float* lw1 = (const float*)d_in[4];
    const float* lb1 = (const float*)d_in[5];
    const float* w2  = (const float*)d_in[6];
    const float* lw2 = (const float*)d_in[7];
    const float* lb2 = (const float*)d_in[8];
    const float* w3  = (const float*)d_in[9];
    const float* lw3 = (const float*)d_in[10];
    const float* lb3 = (const float*)d_in[11];

    int E = in_sizes[1] / 2;
    int N = in_sizes[2];
    if (E > E_MAX) E = E_MAX;
    if (N > N_NODES) N = N_NODES;

    float *xw, *bufA, *bufB;
    cudaGetSymbolAddress((void**)&xw,   g_xw);
    cudaGetSymbolAddress((void**)&bufA, g_bufA);
    cudaGetSymbolAddress((void**)&bufB, g_bufB);
    float* outp = (float*)d_out;

    const int TB = 256;
    int eBlocks = (E + TB - 1) / TB;
    int nBlocks = (N + TB - 1) / TB;

    // preprocessing: indices, degrees, CSR-by-destination
    detect_kernel<<<1, 64>>>((const int*)ei);
    zero_kernel<<<nBlocks, TB>>>(N);
    convert_kernel<<<eBlocks, TB>>>(ei, E);
    degree_kernel<<<eBlocks, TB>>>(E);
    scan_kernel<<<1, 1024>>>(N);
    csr_kernel<<<eBlocks, TB>>>(E);

    int mTiles = (N + 127) / 128;

    // layer 1: in = x, out = bufB  (Dout = 256)
    gemm_dual_kernel<<<dim3(mTiles, 4), 256>>>(x, w1, lw1, lb1, xw, bufB, N, 256, 256);
    aggregate_kernel<<<N, 256>>>(xw, bufB, bufB, 256, 0);

    // layer 2: in = bufB, out = bufA (Dout = 256)
    gemm_dual_kernel<<<dim3(mTiles, 4), 256>>>(bufB, w2, lw2, lb2, xw, bufA, N, 256, 256);
    aggregate_kernel<<<N, 256>>>(xw, bufA, bufA, 256, 0);

    // layer 3: in = bufA, out = d_out (Dout = 128)
    gemm_dual_kernel<<<dim3(mTiles, 2), 256>>>(bufA, w3, lw3, lb3, xw, bufB, N, 256, 128);
    aggregate_kernel<<<N, 128>>>(xw, bufB, outp, 128, 1);
}

// round 14
// speedup vs baseline: 1.0005x; 1.0005x over previous
#include <cuda_runtime.h>
#include <cstdint>
#include <cstdio>

// Problem constants (fixed by the dataset)
#define N_NODES 50000
#define E_MAX   800000
#define D_HID   256
#define D_OUT   128

// ---------------- device scratch (no allocations allowed) ----------------
__device__ int   g_is64;
__device__ int   g_row[E_MAX];
__device__ int   g_col[E_MAX];
__device__ int   g_outdeg[N_NODES];
__device__ int   g_indeg[N_NODES];
__device__ int   g_fill[N_NODES];
__device__ int   g_off[N_NODES + 1];
__device__ int   g_csr_src[E_MAX];
__device__ float g_csr_norm[E_MAX];

__device__ float g_xw[(size_t)N_NODES * D_HID];
__device__ float g_bufA[(size_t)N_NODES * D_HID];
__device__ float g_bufB[(size_t)N_NODES * D_HID];

// ---------------- dtype detection: int64 vs int32 edge_index ----------------
// If int64: high 32-bit words (odd positions) are all zero (indices < 2^31, nonneg).
// If int32: odd positions are random indices in [0, 50000) -> essentially never all zero.
__global__ void detect_kernel(const int* __restrict__ ei_words) {
    __shared__ int nz;
    if (threadIdx.x == 0) nz = 0;
    __syncthreads();
    int w = ei_words[threadIdx.x * 2 + 1];   // odd words 1,3,...,127
    if (w != 0) atomicAdd(&nz, 1);
    __syncthreads();
    if (threadIdx.x == 0) g_is64 = (nz == 0) ? 1 : 0;
}

__global__ void convert_kernel(const void* __restrict__ ei, int E) {
    int i = blockIdx.x * blockDim.x + threadIdx.x;
    if (i >= E) return;
    if (g_is64) {
        const long long* p = (const long long*)ei;
        g_row[i] = (int)p[i];
        g_col[i] = (int)p[(size_t)E + i];
    } else {
        const int* p = (const int*)ei;
        g_row[i] = p[i];
        g_col[i] = p[E + i];
    }
}

__global__ void zero_kernel(int N) {
    int i = blockIdx.x * blockDim.x + threadIdx.x;
    if (i < N) { g_outdeg[i] = 0; g_indeg[i] = 0; g_fill[i] = 0; }
}

__global__ void degree_kernel(int E) {
    int i = blockIdx.x * blockDim.x + threadIdx.x;
    if (i >= E) return;
    atomicAdd(&g_outdeg[g_row[i]], 1);
    atomicAdd(&g_indeg[g_col[i]], 1);
}

// Single-block exclusive scan of g_indeg -> g_off (N up to 50000, 1024 threads).
__global__ void scan_kernel(int N) {
    __shared__ int sm[1024];
    __shared__ int carry;
    int tid = threadIdx.x;
    if (tid == 0) carry = 0;
    __syncthreads();
    for (int base = 0; base < N; base += 1024) {
        int idx = base + tid;
        int v = (idx < N) ? g_indeg[idx] : 0;
        sm[tid] = v;
        __syncthreads();
        // inclusive Hillis-Steele
        #pragma unroll
        for (int off = 1; off < 1024; off <<= 1) {
            int t = sm[tid];
            int add = (tid >= off) ? sm[tid - off] : 0;
            __syncthreads();
            sm[tid] = t + add;
            __syncthreads();
        }
        int incl = sm[tid];
        int c = carry;          // read before update
        if (idx < N) g_off[idx] = c + incl - v;
        int total = sm[1023];
        __syncthreads();
        if (tid == 0) carry = c + total;
        __syncthreads();
    }
    if (tid == 0) g_off[N] = carry;
}

__global__ void csr_kernel(int E) {
    int e = blockIdx.x * blockDim.x + threadIdx.x;
    if (e >= E) return;
    int r = g_row[e], c = g_col[e];
    int pos = g_off[c] + atomicAdd(&g_fill[c], 1);
    g_csr_src[pos]  = r;
    g_csr_norm[pos] = rsqrtf((float)g_outdeg[r] * (float)g_indeg[c]);
}

// ---------------- fused dual GEMM: xw = A@W ; lin = A@LW + bias ----------------
// A: [M, K] row-major (K=256). W, LW: [K, Dout] row-major. Dout in {128, 256}.
// grid.x over 128-row tiles, grid.y over 2*Dout/128 column/matrix tiles.
__global__ __launch_bounds__(256) void gemm_dual_kernel(
    const float* __restrict__ A, const float* __restrict__ W,
    const float* __restrict__ LW, const float* __restrict__ bias,
    float* __restrict__ xwOut, float* __restrict__ linOut,
    int M, int K, int Dout)
{
    __shared__ float As[16][132];   // transposed A tile, padded
    __shared__ float Bs[16][132];

    int tid = threadIdx.x;
    int ntile = Dout >> 7;                    // 128-col tiles per matrix
    int by = blockIdx.y;
    bool isLin = (by >= ntile);
    const float* B = isLin ? LW : W;
    int colBase = (by % ntile) * 128;
    int rowBase = blockIdx.x * 128;

    int tx = tid & 15;
    int ty = tid >> 4;

    float creg[8][8];
    #pragma unroll
    for (int i = 0; i < 8; i++)
        #pragma unroll
        for (int j = 0; j < 8; j++) creg[i][j] = 0.f;

    for (int kt = 0; kt < K; kt += 16) {
        #pragma unroll
        for (int l = 0; l < 2; l++) {
            int idx = tid + l * 256;
            // A tile: 128 rows x 16 cols = 512 float4
            int ar = idx >> 2;
            int ac = (idx & 3) * 4;
            float4 av = make_float4(0.f, 0.f, 0.f, 0.f);
            int gr = rowBase + ar;
            if (gr < M)
                av = *reinterpret_cast<const float4*>(A + (size_t)gr * K + kt + ac);
            As[ac + 0][ar] = av.x;
            As[ac + 1][ar] = av.y;
            As[ac + 2][ar] = av.z;
            As[ac + 3][ar] = av.w;
            // B tile: 16 rows x 128 cols = 512 float4
            int br = idx >> 5;
            int bc = (idx & 31) * 4;
            float4 bv = *reinterpret_cast<const float4*>(B + (size_t)(kt + br) * Dout + colBase + bc);
            *reinterpret_cast<float4*>(&Bs[br][bc]) = bv;
        }
        __syncthreads();
        #pragma unroll
        for (int kk = 0; kk < 16; kk++) {
            float4 a0 = *reinterpret_cast<const float4*>(&As[kk][ty * 8]);
            float4 a1 = *reinterpret_cast<const float4*>(&As[kk][ty * 8 + 4]);
            float4 b0 = *reinterpret_cast<const float4*>(&Bs[kk][tx * 8]);
            float4 b1 = *reinterpret_cast<const float4*>(&Bs[kk][tx * 8 + 4]);
            float a[8] = {a0.x, a0.y, a0.z, a0.w, a1.x, a1.y, a1.z, a1.w};
            float b[8] = {b0.x, b0.y, b0.z, b0.w, b1.x, b1.y, b1.z, b1.w};
            #pragma unroll
            for (int i = 0; i < 8; i++)
                #pragma unroll
                for (int j = 0; j < 8; j++)
                    creg[i][j] = fmaf(a[i], b[j], creg[i][j]);
        }
        __syncthreads();
    }

    float* Cout = isLin ? linOut : xwOut;
    #pragma unroll
    for (int i = 0; i < 8; i++) {
        int r = rowBase + ty * 8 + i;
        if (r >= M) continue;
        int c = colBase + tx * 8;
        float o[8];
        #pragma unroll
        for (int j = 0; j < 8; j++) {
            float v = creg[i][j];
            if (isLin) v += bias[c + j];
            o[j] = v;
        }
        *reinterpret_cast<float4*>(Cout + (size_t)r * Dout + c)     = make_float4(o[0], o[1], o[2], o[3]);
        *reinterpret_cast<float4*>(Cout + (size_t)r * Dout + c + 4) = make_float4(o[4], o[5], o[6], o[7]);
    }
}

// ---------------- aggregation: out[n] = act( lin[n] + sum_e norm[e]*xw[src[e]] ) ----
// One block per destination node, blockDim == Dout. act: 0 = relu, 1 = sigmoid.
__global__ void aggregate_kernel(const float* __restrict__ xw,
                                 const float* __restrict__ lin,
                                 float* __restrict__ out,
                                 int Dout, int act)
{
    __shared__ int   s_src[128];
    __shared__ float s_nrm[128];
    int n = blockIdx.x;
    int f = threadIdx.x;     // < Dout
    int beg = g_off[n], end = g_off[n + 1];
    float sum = 0.f;
    for (int cb = beg; cb < end; cb += 128) {
        int cnt = min(128, end - cb);
        __syncthreads();
        if (f < cnt) {
            s_src[f] = g_csr_src[cb + f];
            s_nrm[f] = g_csr_norm[cb + f];
        }
        __syncthreads();
        #pragma unroll 4
        for (int i = 0; i < cnt; i++)
            sum = fmaf(s_nrm[i], __ldg(&xw[(size_t)s_src[i] * Dout + f]), sum);
    }
    float v = lin[(size_t)n * Dout + f] + sum;
    if (act)
        v = 1.f / (1.f + expf(-v));
    else
        v = fmaxf(v, 0.f);
    out[(size_t)n * Dout + f] = v;
}

// ---------------- launch ----------------
extern "C" void kernel_launch(void* const* d_in, const int* in_sizes, int n_in,
                              void* d_out, int out_size) {
    const float* x   = (const float*)d_in[0];
    const void*  ei  = d_in[1];
    // d_in[2] = batch (unused)
    const float* w1  = (const float*)d_in[3];
    const float* lw1 = (const float*)d_in[4];
    const float* lb1 = (const float*)d_in[5];
    const float* w2  = (const float*)d_in[6];
    const float* lw2 = (const float*)d_in[7];
    const float* lb2 = (const float*)d_in[8];
    const float* w3  = (const float*)d_in[9];
    const float* lw3 = (const float*)d_in[10];
    const float* lb3 = (const float*)d_in[11];

    int E = in_sizes[1] / 2;
    int N = in_sizes[2];
    if (E > E_MAX) E = E_MAX;
    if (N > N_NODES) N = N_NODES;

    float *xw, *bufA, *bufB;
    cudaGetSymbolAddress((void**)&xw,   g_xw);
    cudaGetSymbolAddress((void**)&bufA, g_bufA);
    cudaGetSymbolAddress((void**)&bufB, g_bufB);
    float* outp = (float*)d_out;

    const int TB = 256;
    int eBlocks = (E + TB - 1) / TB;
    int nBlocks = (N + TB - 1) / TB;

    // preprocessing: indices, degrees, CSR-by-destination
    detect_kernel<<<1, 64>>>((const int*)ei);
    zero_kernel<<<nBlocks, TB>>>(N);
    convert_kernel<<<eBlocks, TB>>>(ei, E);
    degree_kernel<<<eBlocks, TB>>>(E);
    scan_kernel<<<1, 1024>>>(N);
    csr_kernel<<<eBlocks, TB>>>(E);

    int mTiles = (N + 127) / 128;

    // layer 1: in = x, out = bufB  (Dout = 256)
    gemm_dual_kernel<<<dim3(mTiles, 4), 256>>>(x, w1, lw1, lb1, xw, bufB, N, 256, 256);
    aggregate_kernel<<<N, 256>>>(xw, bufB, bufB, 256, 0);

    // layer 2: in = bufB, out = bufA (Dout = 256)
    gemm_dual_kernel<<<dim3(mTiles, 4), 256>>>(bufB, w2, lw2, lb2, xw, bufA, N, 256, 256);
    aggregate_kernel<<<N, 256>>>(xw, bufA, bufA, 256, 0);

    // layer 3: in = bufA, out = d_out (Dout = 128)
    gemm_dual_kernel<<<dim3(mTiles, 2), 256>>>(bufA, w3, lw3, lb3, xw, bufB, N, 256, 128);
    aggregate_kernel<<<N, 128>>>(xw, bufB, outp, 128, 1);
}